// round 7
// baseline (speedup 1.0000x reference)
#include <cuda_runtime.h>
#include <cuda_bf16.h>

// Problem constants (fixed by setup_inputs)
#define BS 2
#define LQ 384
#define LK 384
#define NH 8
#define DQ 32
#define DK 32
#define DV 32
#define DC 64
#define BH (BS*NH)          // 16
#define QTILE 8             // q rows per main block (one per warp)
#define NG 3                // float4 groups of k per lane (3*4*32 = 384)

// Scratch (allocation-free rule: __device__ globals), 16B aligned for float4
__device__ __align__(16) float g_qW[BH * LQ * DC];        // [bh][q][e]
__device__ __align__(16) float g_kWT[BH * DC * LK];       // [bh][e][k]  (includes b1)
__device__ __align__(16) float g_att[BH * LQ * LK];       // fallback att buffer

// ---------------------------------------------------------------------------
// Pre-kernel: qW = q @ W1[:DQ]   (layout [bh][q][e], e-coalesced stores)
//             kWbT = (k @ W1[DQ:]) + b1, transposed to [bh][e][k]
// grid (12, 16, 2) block 256
// ---------------------------------------------------------------------------
__global__ void __launch_bounds__(256) pre_kernel(
    const float* __restrict__ qin, const float* __restrict__ kin,
    const float* __restrict__ w1, const float* __restrict__ b1)
{
    __shared__ float w1s[32 * 64];       // [d][e] half of W1 for this head
    __shared__ float rows_s[32 * 33];    // 32 input rows x 32 dims, padded

    const int bh   = blockIdx.y;
    const int b    = bh >> 3;
    const int h    = bh & 7;
    const int row0 = blockIdx.x * 32;
    const int side = blockIdx.z;         // 0 = q-side, 1 = k-side
    const int tid  = threadIdx.x;

    const float* in = side ? kin : qin;
    const int woff = h * (DC * DC) + side * (DQ * DC);  // w1[h][side*32 + d][e]

    for (int i = tid; i < 32 * 64; i += 256) w1s[i] = w1[woff + i];
    {
        const int r = tid >> 5, d = tid & 31;
        #pragma unroll
        for (int p = 0; p < 4; p++) {
            const int rr = p * 8 + r;
            rows_s[rr * 33 + d] = in[(b * LQ + row0 + rr) * (NH * 32) + h * 32 + d];
        }
    }
    __syncthreads();

    if (side == 0) {
        const int el = tid & 63;         // e
        const int rg = tid >> 6;         // 0..3
        #pragma unroll
        for (int i = 0; i < 8; i++) {
            const int r = rg * 8 + i;
            float acc = 0.f;
            #pragma unroll
            for (int d = 0; d < 32; d++)
                acc = fmaf(rows_s[r * 33 + d], w1s[d * 64 + el], acc);
            g_qW[(bh * LQ + row0 + r) * DC + el] = acc;
        }
    } else {
        const int kl = tid & 31;         // k within tile
        const int eg = tid >> 5;         // 0..7
        float acc[8];
        #pragma unroll
        for (int j = 0; j < 8; j++) acc[j] = b1[h * DC + eg * 8 + j];
        #pragma unroll
        for (int d = 0; d < 32; d++) {
            const float rv = rows_s[kl * 33 + d];
            #pragma unroll
            for (int j = 0; j < 8; j++)
                acc[j] = fmaf(rv, w1s[d * 64 + eg * 8 + j], acc[j]);
        }
        #pragma unroll
        for (int j = 0; j < 8; j++)
            g_kWT[(bh * DC + eg * 8 + j) * LK + row0 + kl] = acc[j];
    }
}

// ---------------------------------------------------------------------------
// Main kernel: scores (tanh.approx) + softmax + att store. NO AV here.
// grid (LQ/QTILE=48, BH=16), block 256 (8 warps = 8 q rows), 2 CTAs/SM.
// smem floats: kws[64][384]=24576, qws[8][64]=512, w2s[64] -> 25152 (100.6KB)
// ---------------------------------------------------------------------------
#define SM_KWS   0
#define SM_QWS   24576
#define SM_W2    25088
#define SM_FLOATS 25152
#define SMEM_BYTES (SM_FLOATS * 4)

__global__ void __launch_bounds__(256, 2) main_kernel(
    const int* __restrict__ klens,
    const float* __restrict__ w2g,
    float* __restrict__ attp)
{
    extern __shared__ float sm[];
    float* kws = sm + SM_KWS;
    float* qws = sm + SM_QWS;
    float* w2s = sm + SM_W2;

    const int tid  = threadIdx.x;
    const int w    = tid >> 5;
    const int lane = tid & 31;
    const int bh   = blockIdx.y;
    const int b    = bh >> 3;
    const int h    = bh & 7;
    const int q    = blockIdx.x * QTILE + w;

    // ---- load phase (vectorized) ----
    {
        const float4* src = (const float4*)(g_kWT + bh * (DC * LK));
        float4* dst = (float4*)kws;
        #pragma unroll
        for (int i = 0; i < (DC * LK / 4) / 256; i++)      // 24 iters
            dst[tid + i * 256] = src[tid + i * 256];
    }
    #pragma unroll
    for (int i = tid; i < QTILE * DC; i += 256) {
        const int qq = blockIdx.x * QTILE + (i >> 6);
        qws[i] = g_qW[(bh * LQ + qq) * DC + (i & 63)];
    }
    if (tid < 64) w2s[tid] = w2g[h * DC + tid];
    __syncthreads();

    // ---- score phase: acc = sum_e w2[e]*tanh(qW[e] + kWb[k][e]) ----
    float4 acc[NG];
    #pragma unroll
    for (int g = 0; g < NG; g++) acc[g] = make_float4(0.f, 0.f, 0.f, 0.f);

    #pragma unroll 2
    for (int e = 0; e < DC; e++) {
        const float qe  = qws[w * DC + e];
        const float w2e = w2s[e];
        const float4* kr = ((const float4*)(kws + e * LK)) + lane;
        #pragma unroll
        for (int g = 0; g < NG; g++) {
            const float4 kv = kr[g * 32];
            float t0, t1, t2, t3;
            asm("tanh.approx.f32 %0, %1;" : "=f"(t0) : "f"(kv.x + qe));
            asm("tanh.approx.f32 %0, %1;" : "=f"(t1) : "f"(kv.y + qe));
            asm("tanh.approx.f32 %0, %1;" : "=f"(t2) : "f"(kv.z + qe));
            asm("tanh.approx.f32 %0, %1;" : "=f"(t3) : "f"(kv.w + qe));
            acc[g].x = fmaf(w2e, t0, acc[g].x);
            acc[g].y = fmaf(w2e, t1, acc[g].y);
            acc[g].z = fmaf(w2e, t2, acc[g].z);
            acc[g].w = fmaf(w2e, t3, acc[g].w);
        }
    }

    // ---- softmax over k (warp-wide); masked k -> exact 0 in att ----
    const int klen = klens[b];
    const int kb = lane * 4;
    float m = -3.0e38f;
    #pragma unroll
    for (int g = 0; g < NG; g++) {
        float* a = (float*)&acc[g];
        #pragma unroll
        for (int j = 0; j < 4; j++)
            if (g * 128 + kb + j < klen) m = fmaxf(m, a[j]);
    }
    #pragma unroll
    for (int o = 16; o > 0; o >>= 1) m = fmaxf(m, __shfl_xor_sync(0xffffffffu, m, o));

    float sum = 0.f;
    #pragma unroll
    for (int g = 0; g < NG; g++) {
        float* a = (float*)&acc[g];
        #pragma unroll
        for (int j = 0; j < 4; j++) {
            const float p = (g * 128 + kb + j < klen) ? __expf(a[j] - m) : 0.f;
            a[j] = p;
            sum += p;
        }
    }
    #pragma unroll
    for (int o = 16; o > 0; o >>= 1) sum += __shfl_xor_sync(0xffffffffu, sum, o);
    const float inv = 1.0f / sum;

    const int attbase = (bh * LQ + q) * LK;
    #pragma unroll
    for (int g = 0; g < NG; g++) {
        float4 p4;
        p4.x = acc[g].x * inv; p4.y = acc[g].y * inv;
        p4.z = acc[g].z * inv; p4.w = acc[g].w * inv;
        ((float4*)(attp + attbase + g * 128))[lane] = p4;   // STG.128
    }
}

// ---------------------------------------------------------------------------
// AV kernel: out[b,q,h,d] = sum_k att[bh,q,k] * v[b,k,h,d]; q-length mask.
// grid (LQ/32=12, BH=16), block 256 (8 warps x 4 q rows). att masked-k are 0.
// ---------------------------------------------------------------------------
__global__ void __launch_bounds__(256) av_kernel(
    const float* __restrict__ v,
    const int* __restrict__ qlens,
    const float* __restrict__ attp,
    float* __restrict__ outp)
{
    __shared__ float vs[LK * 32];            // [k][d]  48KB
    __shared__ float pst[8][4][32];          // staged att chunks per warp

    const int tid  = threadIdx.x;
    const int w    = tid >> 5;
    const int lane = tid & 31;
    const int bh   = blockIdx.y;
    const int b    = bh >> 3;
    const int h    = bh & 7;
    const int q0   = blockIdx.x * 32;

    {
        float4* dst = (float4*)vs;
        #pragma unroll
        for (int i = 0; i < (LK * 32 / 4) / 256; i++) {   // 12 iters
            const int idx = tid + i * 256;                // float4 index
            const int row = idx >> 3, c4 = idx & 7;
            dst[idx] = ((const float4*)(v + (b * LK + row) * (NH * 32) + h * 32))[c4];
        }
    }
    __syncthreads();

    const int qb = q0 + w * 4;
    const float* a0 = attp + (bh * LQ + qb + 0) * LK;
    const float* a1 = attp + (bh * LQ + qb + 1) * LK;
    const float* a2 = attp + (bh * LQ + qb + 2) * LK;
    const float* a3 = attp + (bh * LQ + qb + 3) * LK;

    float acc0 = 0.f, acc1 = 0.f, acc2 = 0.f, acc3 = 0.f;

    for (int k0 = 0; k0 < LK; k0 += 32) {
        pst[w][0][lane] = a0[k0 + lane];
        pst[w][1][lane] = a1[k0 + lane];
        pst[w][2][lane] = a2[k0 + lane];
        pst[w][3][lane] = a3[k0 + lane];
        __syncwarp();
        #pragma unroll
        for (int j = 0; j < 32; j += 4) {
            const float4 p0 = *(const float4*)&pst[w][0][j];
            const float4 p1 = *(const float4*)&pst[w][1][j];
            const float4 p2 = *(const float4*)&pst[w][2][j];
            const float4 p3 = *(const float4*)&pst[w][3][j];
            const float v0 = vs[(k0 + j + 0) * 32 + lane];
            const float v1 = vs[(k0 + j + 1) * 32 + lane];
            const float v2 = vs[(k0 + j + 2) * 32 + lane];
            const float v3 = vs[(k0 + j + 3) * 32 + lane];
            acc0 = fmaf(p0.x, v0, acc0); acc0 = fmaf(p0.y, v1, acc0);
            acc0 = fmaf(p0.z, v2, acc0); acc0 = fmaf(p0.w, v3, acc0);
            acc1 = fmaf(p1.x, v0, acc1); acc1 = fmaf(p1.y, v1, acc1);
            acc1 = fmaf(p1.z, v2, acc1); acc1 = fmaf(p1.w, v3, acc1);
            acc2 = fmaf(p2.x, v0, acc2); acc2 = fmaf(p2.y, v1, acc2);
            acc2 = fmaf(p2.z, v2, acc2); acc2 = fmaf(p2.w, v3, acc2);
            acc3 = fmaf(p3.x, v0, acc3); acc3 = fmaf(p3.y, v1, acc3);
            acc3 = fmaf(p3.z, v2, acc3); acc3 = fmaf(p3.w, v3, acc3);
        }
        __syncwarp();
    }

    const int qlen = qlens[b];
    outp[((b * LQ + qb + 0) * NH + h) * 32 + lane] = (qb + 0 < qlen) ? acc0 : 0.f;
    outp[((b * LQ + qb + 1) * NH + h) * 32 + lane] = (qb + 1 < qlen) ? acc1 : 0.f;
    outp[((b * LQ + qb + 2) * NH + h) * 32 + lane] = (qb + 2 < qlen) ? acc2 : 0.f;
    outp[((b * LQ + qb + 3) * NH + h) * 32 + lane] = (qb + 3 < qlen) ? acc3 : 0.f;
}

// ---------------------------------------------------------------------------
extern "C" void kernel_launch(void* const* d_in, const int* in_sizes, int n_in,
                              void* d_out, int out_size)
{
    const float* q    = (const float*)d_in[0];
    const float* k    = (const float*)d_in[1];
    const float* v    = (const float*)d_in[2];
    const int*   qlen = (const int*)  d_in[3];
    const int*   klen = (const int*)  d_in[4];
    const float* w1   = (const float*)d_in[5];
    const float* b1   = (const float*)d_in[6];
    const float* w2   = (const float*)d_in[7];

    float* outp = (float*)d_out;
    const int OUT_ELEMS = BS * LQ * NH * DV;          // 196608
    const int ATT_ELEMS = BH * LQ * LK;               // 2359296
    float* attp = (out_size >= OUT_ELEMS + ATT_ELEMS) ? (outp + OUT_ELEMS)
                                                      : (float*)g_att;

    pre_kernel<<<dim3(LQ / 32, BH, 2), 256>>>(q, k, w1, b1);

    cudaFuncSetAttribute(main_kernel, cudaFuncAttributeMaxDynamicSharedMemorySize, SMEM_BYTES);
    main_kernel<<<dim3(LQ / QTILE, BH), 256, SMEM_BYTES>>>(klen, w2, attp);

    av_kernel<<<dim3(LQ / 32, BH), 256>>>(v, qlen, attp, outp);
}